// round 8
// baseline (speedup 1.0000x reference)
#include <cuda_runtime.h>
#include <cuda_bf16.h>
#include <math.h>
#include <stdint.h>

#define NTOK 16384
#define KDIM 768
#define KHID 3072
#define NEXP 5

// ---------------- device scratch (static, allocation-free) ----------------
__device__ int   g_count[NEXP];
__device__ int   g_tok[NEXP * NTOK];
__device__ float g_gate[NEXP * NTOK];
__device__ float g_H[(size_t)NTOK * KHID];   // fp32 hidden scratch

// ---------------- helpers ----------------
__device__ __forceinline__ void mma16816(float (&c)[4], const uint32_t (&a)[4],
                                         uint32_t b0, uint32_t b1) {
    asm volatile("mma.sync.aligned.m16n8k16.row.col.f32.bf16.bf16.f32 "
                 "{%0,%1,%2,%3}, {%4,%5,%6,%7}, {%8,%9}, {%0,%1,%2,%3};"
                 : "+f"(c[0]), "+f"(c[1]), "+f"(c[2]), "+f"(c[3])
                 : "r"(a[0]), "r"(a[1]), "r"(a[2]), "r"(a[3]), "r"(b0), "r"(b1));
}
// split (fx, fy) -> packed bf16x2 hi and bf16x2 lo (residual)
__device__ __forceinline__ void split2(float fx, float fy, uint32_t& hi, uint32_t& lo) {
    uint32_t h;
    asm("cvt.rn.bf16x2.f32 %0, %1, %2;" : "=r"(h) : "f"(fy), "f"(fx));
    float lx = fx - __uint_as_float(h << 16);
    float ly = fy - __uint_as_float(h & 0xffff0000u);
    asm("cvt.rn.bf16x2.f32 %0, %1, %2;" : "=r"(lo) : "f"(ly), "f"(lx));
    hi = h;
}
__device__ __forceinline__ float gelu_erf(float v) {
    return 0.5f * v * (1.0f + erff(v * 0.70710678118654752f));
}

// ---------------------------------------------------------------------------
__global__ void zero_counts_kernel() {
    if (threadIdx.x < NEXP) g_count[threadIdx.x] = 0;
}

__global__ void gating_kernel(const float* __restrict__ x, const float* __restrict__ wg) {
    int t = (blockIdx.x * blockDim.x + threadIdx.x) >> 5;
    int lane = threadIdx.x & 31;
    if (t >= NTOK) return;
    const float* xr = x + (size_t)t * KDIM;
    float p0 = 0.f, p1 = 0.f, p2 = 0.f, p3 = 0.f, p4 = 0.f;
    for (int k = lane; k < KDIM; k += 32) {
        float xv = xr[k];
        const float* w = wg + (size_t)k * NEXP;
        p0 += xv * w[0]; p1 += xv * w[1]; p2 += xv * w[2]; p3 += xv * w[3]; p4 += xv * w[4];
    }
#pragma unroll
    for (int o = 16; o > 0; o >>= 1) {
        p0 += __shfl_down_sync(0xffffffffu, p0, o);
        p1 += __shfl_down_sync(0xffffffffu, p1, o);
        p2 += __shfl_down_sync(0xffffffffu, p2, o);
        p3 += __shfl_down_sync(0xffffffffu, p3, o);
        p4 += __shfl_down_sync(0xffffffffu, p4, o);
    }
    if (lane == 0) {
        float v[NEXP] = {p0, p1, p2, p3, p4};
        int i0 = 0; float v0 = v[0];
#pragma unroll
        for (int e = 1; e < NEXP; e++) if (v[e] > v0) { v0 = v[e]; i0 = e; }
        int i1 = -1; float v1 = -3.4e38f;
#pragma unroll
        for (int e = 0; e < NEXP; e++) if (e != i0 && v[e] > v1) { v1 = v[e]; i1 = e; }
        float e1 = expf(v1 - v0);
        float s = 1.0f + e1;
        int q0 = atomicAdd(&g_count[i0], 1);
        g_tok[i0 * NTOK + q0] = t;  g_gate[i0 * NTOK + q0] = 1.0f / s;
        int q1 = atomicAdd(&g_count[i1], 1);
        g_tok[i1 * NTOK + q1] = t;  g_gate[i1 * NTOK + q1] = e1 / s;
    }
}

// ---------------------------------------------------------------------------
// GEMM: 128x128 CTA tile, 512 threads, 16 warps in 4x4 grid, warp tile 32x32,
// fp32 LDG->STS double buffer, in-register bf16 hi/lo split, 3-term mma.
#define CKE 16
#define A_STR 20     // floats per SMEM A row (16 + pad)
#define B_STR 136    // floats per SMEM B row (128 + pad)

// MODE 0 (fc1): A = gathered x rows [*,768], B = W1[e] [768,3072]; epi: g_H = gelu(acc+b1)
// MODE 1 (fc2): A = g_H [*,3072],          B = W2[e] [3072,768]; epi: out[tok] += gate*exp(acc+b2)
template <int MODE>
__global__ __launch_bounds__(512, 1)
void moe_mma_kernel(const float* __restrict__ x, const float* __restrict__ W,
                    const float* __restrict__ bias, int e, float* __restrict__ out) {
    int cnt = g_count[e];
    int row0 = blockIdx.y * 128;
    if (row0 >= cnt) return;
    int col0 = blockIdx.x * 128;

    const int KE = (MODE == 0) ? KDIM : KHID;   // reduction length
    const int NB = (MODE == 0) ? KHID : KDIM;   // output width (B row stride)

    __shared__ float sA[2][128 * A_STR];
    __shared__ float sB[2][CKE * B_STR];
    __shared__ float s_bias[128];

    int tid = threadIdx.x, wid = tid >> 5, lane = tid & 31;
    int wm = (wid & 3) * 32, wn = (wid >> 2) * 32;   // 4x4 warp grid, 32x32 tiles
    int g = lane >> 2, t4 = lane & 3;

    if (tid < 128) s_bias[tid] = bias[(size_t)e * NB + col0 + tid];

    // A loader: thread -> (row lr, float4 at k=lq). 512 thr x 1 float4 = 128x16.
    int lr = tid >> 2, lq = (tid & 3) * 4;
    int arow = row0 + lr;
    const float* aSrc;
    if (MODE == 0) {
        int tokA = g_tok[e * NTOK + (arow < cnt ? arow : row0)];
        aSrc = x + (size_t)tokA * KDIM + lq;
    } else {
        aSrc = g_H + (size_t)arow * KHID + lq;   // garbage rows >= cnt: finite, discarded
    }
    // B loader: thread -> (k-row kr, float4 at n=seg*4). 512 thr x 1 float4 = 16x128.
    int kr = tid >> 5, seg = tid & 31;
    const float* bSrc = W + (size_t)e * KDIM * KHID + (size_t)kr * NB + col0 + seg * 4;

    float4 ra, rb;
    auto ldg = [&](int c) {
        ra = *(const float4*)(aSrc + c * CKE);
        rb = *(const float4*)(bSrc + (size_t)c * CKE * NB);
    };
    auto sts = [&](int s) {
        *(float4*)&sA[s][lr * A_STR + lq] = ra;
        *(float4*)&sB[s][kr * B_STR + seg * 4] = rb;
    };

    float acc[2][4][4];
#pragma unroll
    for (int i = 0; i < 2; i++)
#pragma unroll
        for (int j = 0; j < 4; j++)
#pragma unroll
            for (int k = 0; k < 4; k++) acc[i][j][k] = 0.f;

    const int NC = KE / CKE;
    ldg(0);
    sts(0);

    for (int c = 0; c < NC; c++) {
        __syncthreads();
        if (c + 1 < NC) ldg(c + 1);

        const float* A = sA[c & 1];
        const float* B = sB[c & 1];

        // A fragments: a0=(row g, k 2t4..+1), a1=(g+8,k), a2=(g,k+8), a3=(g+8,k+8)
        uint32_t ah[2][4], al[2][4];
#pragma unroll
        for (int mt = 0; mt < 2; mt++) {
            int r0 = wm + mt * 16 + g;
            float2 f0 = *(const float2*)&A[r0 * A_STR + 2 * t4];
            float2 f1 = *(const float2*)&A[(r0 + 8) * A_STR + 2 * t4];
            float2 f2 = *(const float2*)&A[r0 * A_STR + 2 * t4 + 8];
            float2 f3 = *(const float2*)&A[(r0 + 8) * A_STR + 2 * t4 + 8];
            split2(f0.x, f0.y, ah[mt][0], al[mt][0]);
            split2(f1.x, f1.y, ah[mt][1], al[mt][1]);
            split2(f2.x, f2.y, ah[mt][2], al[mt][2]);
            split2(f3.x, f3.y, ah[mt][3], al[mt][3]);
        }
#pragma unroll
        for (int np = 0; np < 2; np++) {
            int n0 = wn + np * 16 + g;
            uint32_t bh[4], bl[4];
            split2(B[(2 * t4) * B_STR + n0],         B[(2 * t4 + 1) * B_STR + n0],     bh[0], bl[0]);
            split2(B[(2 * t4 + 8) * B_STR + n0],     B[(2 * t4 + 9) * B_STR + n0],     bh[1], bl[1]);
            split2(B[(2 * t4) * B_STR + n0 + 8],     B[(2 * t4 + 1) * B_STR + n0 + 8], bh[2], bl[2]);
            split2(B[(2 * t4 + 8) * B_STR + n0 + 8], B[(2 * t4 + 9) * B_STR + n0 + 8], bh[3], bl[3]);
#pragma unroll
            for (int mt = 0; mt < 2; mt++) {
                mma16816(acc[mt][np * 2 + 0], ah[mt], bh[0], bh[1]);
                mma16816(acc[mt][np * 2 + 0], al[mt], bh[0], bh[1]);
                mma16816(acc[mt][np * 2 + 0], ah[mt], bl[0], bl[1]);
                mma16816(acc[mt][np * 2 + 1], ah[mt], bh[2], bh[3]);
                mma16816(acc[mt][np * 2 + 1], al[mt], bh[2], bh[3]);
                mma16816(acc[mt][np * 2 + 1], ah[mt], bl[2], bl[3]);
            }
        }
        if (c + 1 < NC) sts((c + 1) & 1);
    }

    // ---- epilogue: fragment rows g / g+8; cols wn + nj*8 + 2*t4 + {0,1}, nj 0..3
#pragma unroll
    for (int mt = 0; mt < 2; mt++) {
        int gr0 = row0 + wm + mt * 16 + g;
        int gr1 = gr0 + 8;
        bool a0 = gr0 < cnt, a1 = gr1 < cnt;
        int tok0 = 0, tok1 = 0; float gt0 = 0.f, gt1 = 0.f;
        if (MODE == 1) {
            if (a0) { tok0 = g_tok[e * NTOK + gr0]; gt0 = g_gate[e * NTOK + gr0]; }
            if (a1) { tok1 = g_tok[e * NTOK + gr1]; gt1 = g_gate[e * NTOK + gr1]; }
        }
#pragma unroll
        for (int nj = 0; nj < 4; nj++) {
            int cloc = wn + nj * 8 + 2 * t4;
            float b0v = s_bias[cloc], b1v = s_bias[cloc + 1];
            if (MODE == 0) {
                size_t o0 = (size_t)gr0 * KHID + col0 + cloc;
                size_t o1 = (size_t)gr1 * KHID + col0 + cloc;
                if (a0) {
                    g_H[o0]     = gelu_erf(acc[mt][nj][0] + b0v);
                    g_H[o0 + 1] = gelu_erf(acc[mt][nj][1] + b1v);
                }
                if (a1) {
                    g_H[o1]     = gelu_erf(acc[mt][nj][2] + b0v);
                    g_H[o1 + 1] = gelu_erf(acc[mt][nj][3] + b1v);
                }
            } else {
                int cb = col0 + cloc;
                if (a0) {
                    float* op = out + (size_t)tok0 * KDIM + cb;
                    op[0] += gt0 * expf(acc[mt][nj][0] + b0v);
                    op[1] += gt0 * expf(acc[mt][nj][1] + b1v);
                }
                if (a1) {
                    float* op = out + (size_t)tok1 * KDIM + cb;
                    op[0] += gt1 * expf(acc[mt][nj][2] + b0v);
                    op[1] += gt1 * expf(acc[mt][nj][3] + b1v);
                }
            }
        }
    }
}

// ---------------------------------------------------------------------------
__global__ void finalize_kernel(float* __restrict__ out, int n) {
    int i = blockIdx.x * blockDim.x + threadIdx.x;
    if (i < n) {
        float v = out[i];
        out[i] = logf(v == 0.0f ? 2.2204460492503131e-16f : v);
    }
}

// ---------------------------------------------------------------------------
extern "C" void kernel_launch(void* const* d_in, const int* in_sizes, int n_in,
                              void* d_out, int out_size) {
    const float* x  = (const float*)d_in[0];
    const float* wg = (const float*)d_in[1];
    const float* W1 = (const float*)d_in[2];
    const float* b1 = (const float*)d_in[3];
    const float* W2 = (const float*)d_in[4];
    const float* b2 = (const float*)d_in[5];
    float* out = (float*)d_out;

    cudaMemsetAsync(out, 0, (size_t)NTOK * KDIM * sizeof(float), 0);
    zero_counts_kernel<<<1, 32>>>();
    gating_kernel<<<(NTOK * 32 + 255) / 256, 256>>>(x, wg);

    for (int e = 0; e < NEXP; e++) {
        dim3 g1(KHID / 128, NTOK / 128);   // (24, 128)
        moe_mma_kernel<0><<<g1, 512>>>(x, W1, b1, e, out);
        dim3 g2(KDIM / 128, NTOK / 128);   // (6, 128)
        moe_mma_kernel<1><<<g2, 512>>>(g_H, W2, b2, e, out);
    }

    finalize_kernel<<<(NTOK * KDIM + 255) / 256, 256>>>(out, NTOK * KDIM);
}

// round 9
// speedup vs baseline: 1.0525x; 1.0525x over previous
#include <cuda_runtime.h>
#include <cuda_bf16.h>
#include <math.h>
#include <stdint.h>

#define NTOK 16384
#define KDIM 768
#define KHID 3072
#define NEXP 5

// ---------------- device scratch (static, allocation-free) ----------------
__device__ int   g_count[NEXP];
__device__ int   g_tok[NEXP * NTOK];
__device__ float g_gate[NEXP * NTOK];
__device__ float g_H[(size_t)NTOK * KHID];   // fp32 hidden scratch

// ---------------- helpers ----------------
__device__ __forceinline__ void mma16816(float (&c)[4], const uint32_t (&a)[4],
                                         uint32_t b0, uint32_t b1) {
    asm volatile("mma.sync.aligned.m16n8k16.row.col.f32.bf16.bf16.f32 "
                 "{%0,%1,%2,%3}, {%4,%5,%6,%7}, {%8,%9}, {%0,%1,%2,%3};"
                 : "+f"(c[0]), "+f"(c[1]), "+f"(c[2]), "+f"(c[3])
                 : "r"(a[0]), "r"(a[1]), "r"(a[2]), "r"(a[3]), "r"(b0), "r"(b1));
}
// split (fx, fy) -> packed bf16x2 hi (fx low) and bf16x2 lo (residual)
__device__ __forceinline__ void split2(float fx, float fy, uint32_t& hi, uint32_t& lo) {
    uint32_t h;
    asm("cvt.rn.bf16x2.f32 %0, %1, %2;" : "=r"(h) : "f"(fy), "f"(fx));
    float lx = fx - __uint_as_float(h << 16);
    float ly = fy - __uint_as_float(h & 0xffff0000u);
    asm("cvt.rn.bf16x2.f32 %0, %1, %2;" : "=r"(lo) : "f"(ly), "f"(lx));
    hi = h;
}
__device__ __forceinline__ float gelu_erf(float v) {
    return 0.5f * v * (1.0f + erff(v * 0.70710678118654752f));
}

// ---------------------------------------------------------------------------
__global__ void zero_counts_kernel() {
    if (threadIdx.x < NEXP) g_count[threadIdx.x] = 0;
}

__global__ void gating_kernel(const float* __restrict__ x, const float* __restrict__ wg) {
    int t = (blockIdx.x * blockDim.x + threadIdx.x) >> 5;
    int lane = threadIdx.x & 31;
    if (t >= NTOK) return;
    const float* xr = x + (size_t)t * KDIM;
    float p0 = 0.f, p1 = 0.f, p2 = 0.f, p3 = 0.f, p4 = 0.f;
    for (int k = lane; k < KDIM; k += 32) {
        float xv = xr[k];
        const float* w = wg + (size_t)k * NEXP;
        p0 += xv * w[0]; p1 += xv * w[1]; p2 += xv * w[2]; p3 += xv * w[3]; p4 += xv * w[4];
    }
#pragma unroll
    for (int o = 16; o > 0; o >>= 1) {
        p0 += __shfl_down_sync(0xffffffffu, p0, o);
        p1 += __shfl_down_sync(0xffffffffu, p1, o);
        p2 += __shfl_down_sync(0xffffffffu, p2, o);
        p3 += __shfl_down_sync(0xffffffffu, p3, o);
        p4 += __shfl_down_sync(0xffffffffu, p4, o);
    }
    if (lane == 0) {
        float v[NEXP] = {p0, p1, p2, p3, p4};
        int i0 = 0; float v0 = v[0];
#pragma unroll
        for (int e = 1; e < NEXP; e++) if (v[e] > v0) { v0 = v[e]; i0 = e; }
        int i1 = -1; float v1 = -3.4e38f;
#pragma unroll
        for (int e = 0; e < NEXP; e++) if (e != i0 && v[e] > v1) { v1 = v[e]; i1 = e; }
        float e1 = expf(v1 - v0);
        float s = 1.0f + e1;
        int q0 = atomicAdd(&g_count[i0], 1);
        g_tok[i0 * NTOK + q0] = t;  g_gate[i0 * NTOK + q0] = 1.0f / s;
        int q1 = atomicAdd(&g_count[i1], 1);
        g_tok[i1 * NTOK + q1] = t;  g_gate[i1 * NTOK + q1] = e1 / s;
    }
}

// ---------------------------------------------------------------------------
// GEMM: 128x128 CTA tile, 256 threads, 8 warps (4x2), warp tile 32x64.
// Loader pre-splits fp32 -> bf16 (hi,lo) ONCE per value, stores uint2{hi,lo}
// in k-pair-major SMEM: tile[kp][idx], kp 0..7, stride 132 uint2 (132%16==4
// -> fragment LDS.64 bank-pair = 4*t4 + g : conflict-free per 16-lane phase).
// Mainloop: pure LDS.64 + mma (no ALU). 3-term split mma: ahbh + albh + ahbl.
#define CKE 16
#define KPS 132   // uint2 stride between kpair rows
// tile = 8 * 132 uint2 = 8448 B

// MODE 0 (fc1): A = gathered x rows [*,768], B = W1[e] [768,3072]; epi: g_H = gelu(acc+b1)
// MODE 1 (fc2): A = g_H [*,3072],          B = W2[e] [3072,768]; epi: out[tok] += gate*exp(acc+b2)
template <int MODE>
__global__ __launch_bounds__(256, 1)
void moe_mma_kernel(const float* __restrict__ x, const float* __restrict__ W,
                    const float* __restrict__ bias, int e, float* __restrict__ out) {
    int cnt = g_count[e];
    int row0 = blockIdx.y * 128;
    if (row0 >= cnt) return;
    int col0 = blockIdx.x * 128;

    const int KE = (MODE == 0) ? KDIM : KHID;   // reduction length
    const int NB = (MODE == 0) ? KHID : KDIM;   // output width (B row stride)

    __shared__ uint2 sA[2][8 * KPS];
    __shared__ uint2 sB[2][8 * KPS];
    __shared__ float s_bias[128];

    int tid = threadIdx.x, wid = tid >> 5, lane = tid & 31;
    int wm = (wid & 3) * 32, wn = (wid >> 2) * 64;   // 4x2 warp grid, 32x64 tiles
    int g = lane >> 2, t4 = lane & 3;

    if (tid < 128) s_bias[tid] = bias[(size_t)e * NB + col0 + tid];

    // ---- A loader: thread -> quad q (k = 4q..4q+3), rows r0 and r0+64
    int q = tid & 3, r0 = tid >> 2;       // r0 in 0..63
    const float *aSrc0, *aSrc1;
    if (MODE == 0) {
        int ga0 = row0 + r0, ga1 = row0 + r0 + 64;
        int tok0 = g_tok[e * NTOK + (ga0 < cnt ? ga0 : row0)];
        int tok1 = g_tok[e * NTOK + (ga1 < cnt ? ga1 : row0)];
        aSrc0 = x + (size_t)tok0 * KDIM + q * 4;
        aSrc1 = x + (size_t)tok1 * KDIM + q * 4;
    } else {
        aSrc0 = g_H + (size_t)(row0 + r0) * KHID + q * 4;        // rows >= cnt: finite garbage
        aSrc1 = g_H + (size_t)(row0 + r0 + 64) * KHID + q * 4;
    }
    // ---- B loader: thread -> kpair kp (k rows 2kp, 2kp+1), 4 cols at n4
    int kp = tid >> 5, n4 = (tid & 31) * 4;
    const float* bSrc0 = W + (size_t)e * KDIM * KHID + (size_t)(2 * kp) * NB + col0 + n4;
    const float* bSrc1 = bSrc0 + NB;

    float4 va0, va1, vb0, vb1;
    auto ldg = [&](int c) {
        va0 = *(const float4*)(aSrc0 + c * CKE);
        va1 = *(const float4*)(aSrc1 + c * CKE);
        vb0 = *(const float4*)(bSrc0 + (size_t)c * CKE * NB);
        vb1 = *(const float4*)(bSrc1 + (size_t)c * CKE * NB);
    };
    auto sts = [&](int s) {
        uint32_t h, l;
        // A: float4 = kpairs {2q, 2q+1} for rows r0, r0+64
        split2(va0.x, va0.y, h, l); sA[s][(2 * q) * KPS + r0]           = make_uint2(h, l);
        split2(va0.z, va0.w, h, l); sA[s][(2 * q + 1) * KPS + r0]       = make_uint2(h, l);
        split2(va1.x, va1.y, h, l); sA[s][(2 * q) * KPS + r0 + 64]      = make_uint2(h, l);
        split2(va1.z, va1.w, h, l); sA[s][(2 * q + 1) * KPS + r0 + 64]  = make_uint2(h, l);
        // B: pair across k rows -> 4 packed words at (kp, n4..n4+3), 2x STS.128
        uint32_t h0, l0, h1, l1, h2, l2, h3, l3;
        split2(vb0.x, vb1.x, h0, l0);
        split2(vb0.y, vb1.y, h1, l1);
        split2(vb0.z, vb1.z, h2, l2);
        split2(vb0.w, vb1.w, h3, l3);
        uint4* p = (uint4*)&sB[s][kp * KPS + n4];
        p[0] = make_uint4(h0, l0, h1, l1);
        p[1] = make_uint4(h2, l2, h3, l3);
    };

    float acc[2][8][4];
#pragma unroll
    for (int i = 0; i < 2; i++)
#pragma unroll
        for (int j = 0; j < 8; j++)
#pragma unroll
            for (int k = 0; k < 4; k++) acc[i][j][k] = 0.f;

    const int NC = KE / CKE;
    ldg(0);
    sts(0);

    for (int c = 0; c < NC; c++) {
        __syncthreads();
        if (c + 1 < NC) ldg(c + 1);

        const uint2* A = sA[c & 1];
        const uint2* B = sB[c & 1];

        // A fragments: a0=(row,kp t4) a1=(row+8,t4) a2=(row,t4+4) a3=(row+8,t4+4)
        uint32_t ah[2][4], al[2][4];
#pragma unroll
        for (int mt = 0; mt < 2; mt++) {
            int r = wm + mt * 16 + g;
            uint2 w0 = A[t4 * KPS + r];
            uint2 w1 = A[t4 * KPS + r + 8];
            uint2 w2 = A[(t4 + 4) * KPS + r];
            uint2 w3 = A[(t4 + 4) * KPS + r + 8];
            ah[mt][0] = w0.x; al[mt][0] = w0.y;
            ah[mt][1] = w1.x; al[mt][1] = w1.y;
            ah[mt][2] = w2.x; al[mt][2] = w2.y;
            ah[mt][3] = w3.x; al[mt][3] = w3.y;
        }
#pragma unroll
        for (int np = 0; np < 4; np++) {
            int n0 = wn + np * 16 + g;
            uint2 u0 = B[t4 * KPS + n0];
            uint2 u1 = B[(t4 + 4) * KPS + n0];
            uint2 u2 = B[t4 * KPS + n0 + 8];
            uint2 u3 = B[(t4 + 4) * KPS + n0 + 8];
            // interleave across the two accumulators to shorten RAW chains
#pragma unroll
            for (int mt = 0; mt < 2; mt++) {
                mma16816(acc[mt][np * 2 + 0], ah[mt], u0.x, u1.x);
                mma16816(acc[mt][np * 2 + 1], ah[mt], u2.x, u3.x);
                mma16816(acc[mt][np * 2 + 0], al[mt], u0.x, u1.x);
                mma16816(acc[mt][np * 2 + 1], al[mt], u2.x, u3.x);
                mma16816(acc[mt][np * 2 + 0], ah[mt], u0.y, u1.y);
                mma16816(acc[mt][np * 2 + 1], ah[mt], u2.y, u3.y);
            }
        }
        if (c + 1 < NC) sts((c + 1) & 1);
    }

    // ---- epilogue: fragment rows g / g+8; cols wn + nj*8 + 2*t4 + {0,1}
#pragma unroll
    for (int mt = 0; mt < 2; mt++) {
        int gr0 = row0 + wm + mt * 16 + g;
        int gr1 = gr0 + 8;
        bool a0 = gr0 < cnt, a1 = gr1 < cnt;
        int tok0 = 0, tok1 = 0; float gt0 = 0.f, gt1 = 0.f;
        if (MODE == 1) {
            if (a0) { tok0 = g_tok[e * NTOK + gr0]; gt0 = g_gate[e * NTOK + gr0]; }
            if (a1) { tok1 = g_tok[e * NTOK + gr1]; gt1 = g_gate[e * NTOK + gr1]; }
        }
#pragma unroll
        for (int nj = 0; nj < 8; nj++) {
            int cloc = wn + nj * 8 + 2 * t4;
            float b0v = s_bias[cloc], b1v = s_bias[cloc + 1];
            if (MODE == 0) {
                size_t o0 = (size_t)gr0 * KHID + col0 + cloc;
                size_t o1 = (size_t)gr1 * KHID + col0 + cloc;
                if (a0) {
                    g_H[o0]     = gelu_erf(acc[mt][nj][0] + b0v);
                    g_H[o0 + 1] = gelu_erf(acc[mt][nj][1] + b1v);
                }
                if (a1) {
                    g_H[o1]     = gelu_erf(acc[mt][nj][2] + b0v);
                    g_H[o1 + 1] = gelu_erf(acc[mt][nj][3] + b1v);
                }
            } else {
                int cb = col0 + cloc;
                if (a0) {
                    float* op = out + (size_t)tok0 * KDIM + cb;
                    op[0] += gt0 * expf(acc[mt][nj][0] + b0v);
                    op[1] += gt0 * expf(acc[mt][nj][1] + b1v);
                }
                if (a1) {
                    float* op = out + (size_t)tok1 * KDIM + cb;
                    op[0] += gt1 * expf(acc[mt][nj][2] + b0v);
                    op[1] += gt1 * expf(acc[mt][nj][3] + b1v);
                }
            }
        }
    }
}

// ---------------------------------------------------------------------------
__global__ void finalize_kernel(float* __restrict__ out, int n) {
    int i = blockIdx.x * blockDim.x + threadIdx.x;
    if (i < n) {
        float v = out[i];
        out[i] = logf(v == 0.0f ? 2.2204460492503131e-16f : v);
    }
}

// ---------------------------------------------------------------------------
extern "C" void kernel_launch(void* const* d_in, const int* in_sizes, int n_in,
                              void* d_out, int out_size) {
    const float* x  = (const float*)d_in[0];
    const float* wg = (const float*)d_in[1];
    const float* W1 = (const float*)d_in[2];
    const float* b1 = (const float*)d_in[3];
    const float* W2 = (const float*)d_in[4];
    const float* b2 = (const float*)d_in[5];
    float* out = (float*)d_out;

    cudaMemsetAsync(out, 0, (size_t)NTOK * KDIM * sizeof(float), 0);
    zero_counts_kernel<<<1, 32>>>();
    gating_kernel<<<(NTOK * 32 + 255) / 256, 256>>>(x, wg);

    for (int e = 0; e < NEXP; e++) {
        dim3 g1(KHID / 128, NTOK / 128);   // (24, 128)
        moe_mma_kernel<0><<<g1, 256>>>(x, W1, b1, e, out);
        dim3 g2(KDIM / 128, NTOK / 128);   // (6, 128)
        moe_mma_kernel<1><<<g2, 256>>>(g_H, W2, b2, e, out);
    }

    finalize_kernel<<<(NTOK * KDIM + 255) / 256, 256>>>(out, NTOK * KDIM);
}

// round 10
// speedup vs baseline: 1.3867x; 1.3175x over previous
#include <cuda_runtime.h>
#include <cuda_bf16.h>
#include <math.h>
#include <stdint.h>

#define NTOK 16384
#define KDIM 768
#define KHID 3072
#define NEXP 5

// ---------------- device scratch (static, allocation-free) ----------------
__device__ int   g_count[NEXP];
__device__ int   g_tok[NEXP * NTOK];
__device__ float g_gate[NEXP * NTOK];
__device__ float g_H[(size_t)NTOK * KHID];   // fp32 hidden scratch

// ---------------- helpers ----------------
__device__ __forceinline__ uint32_t smem_u32(const void* p) {
    uint32_t a;
    asm("{ .reg .u64 t; cvta.to.shared.u64 t, %1; cvt.u32.u64 %0, t; }" : "=r"(a) : "l"(p));
    return a;
}
__device__ __forceinline__ void mma16816(float (&c)[4], const uint32_t (&a)[4],
                                         uint32_t b0, uint32_t b1) {
    asm volatile("mma.sync.aligned.m16n8k16.row.col.f32.bf16.bf16.f32 "
                 "{%0,%1,%2,%3}, {%4,%5,%6,%7}, {%8,%9}, {%0,%1,%2,%3};"
                 : "+f"(c[0]), "+f"(c[1]), "+f"(c[2]), "+f"(c[3])
                 : "r"(a[0]), "r"(a[1]), "r"(a[2]), "r"(a[3]), "r"(b0), "r"(b1));
}
__device__ __forceinline__ void ldsm4(uint32_t (&d)[4], uint32_t addr) {
    asm volatile("ldmatrix.sync.aligned.m8n8.x4.shared.b16 {%0,%1,%2,%3}, [%4];"
                 : "=r"(d[0]), "=r"(d[1]), "=r"(d[2]), "=r"(d[3]) : "r"(addr));
}
__device__ __forceinline__ void ldsm4t(uint32_t (&d)[4], uint32_t addr) {
    asm volatile("ldmatrix.sync.aligned.m8n8.x4.trans.shared.b16 {%0,%1,%2,%3}, [%4];"
                 : "=r"(d[0]), "=r"(d[1]), "=r"(d[2]), "=r"(d[3]) : "r"(addr));
}
// split (fx, fy) -> packed bf16x2 hi (fx in low half) and bf16x2 lo (residual)
__device__ __forceinline__ void split2(float fx, float fy, uint32_t& hi, uint32_t& lo) {
    uint32_t h;
    asm("cvt.rn.bf16x2.f32 %0, %1, %2;" : "=r"(h) : "f"(fy), "f"(fx));
    float lx = fx - __uint_as_float(h << 16);
    float ly = fy - __uint_as_float(h & 0xffff0000u);
    asm("cvt.rn.bf16x2.f32 %0, %1, %2;" : "=r"(lo) : "f"(ly), "f"(lx));
    hi = h;
}
__device__ __forceinline__ float gelu_erf(float v) {
    return 0.5f * v * (1.0f + erff(v * 0.70710678118654752f));
}

// ---------------------------------------------------------------------------
__global__ void zero_counts_kernel() {
    if (threadIdx.x < NEXP) g_count[threadIdx.x] = 0;
}

__global__ void gating_kernel(const float* __restrict__ x, const float* __restrict__ wg) {
    int t = (blockIdx.x * blockDim.x + threadIdx.x) >> 5;
    int lane = threadIdx.x & 31;
    if (t >= NTOK) return;
    const float* xr = x + (size_t)t * KDIM;
    float p0 = 0.f, p1 = 0.f, p2 = 0.f, p3 = 0.f, p4 = 0.f;
    for (int k = lane; k < KDIM; k += 32) {
        float xv = xr[k];
        const float* w = wg + (size_t)k * NEXP;
        p0 += xv * w[0]; p1 += xv * w[1]; p2 += xv * w[2]; p3 += xv * w[3]; p4 += xv * w[4];
    }
#pragma unroll
    for (int o = 16; o > 0; o >>= 1) {
        p0 += __shfl_down_sync(0xffffffffu, p0, o);
        p1 += __shfl_down_sync(0xffffffffu, p1, o);
        p2 += __shfl_down_sync(0xffffffffu, p2, o);
        p3 += __shfl_down_sync(0xffffffffu, p3, o);
        p4 += __shfl_down_sync(0xffffffffu, p4, o);
    }
    if (lane == 0) {
        float v[NEXP] = {p0, p1, p2, p3, p4};
        int i0 = 0; float v0 = v[0];
#pragma unroll
        for (int e = 1; e < NEXP; e++) if (v[e] > v0) { v0 = v[e]; i0 = e; }
        int i1 = -1; float v1 = -3.4e38f;
#pragma unroll
        for (int e = 0; e < NEXP; e++) if (e != i0 && v[e] > v1) { v1 = v[e]; i1 = e; }
        float e1 = expf(v1 - v0);
        float s = 1.0f + e1;
        int q0 = atomicAdd(&g_count[i0], 1);
        g_tok[i0 * NTOK + q0] = t;  g_gate[i0 * NTOK + q0] = 1.0f / s;
        int q1 = atomicAdd(&g_count[i1], 1);
        g_tok[i1 * NTOK + q1] = t;  g_gate[i1 * NTOK + q1] = e1 / s;
    }
}

// ---------------------------------------------------------------------------
// GEMM: 128x128 CTA tile, 256 threads, 8 warps (4x2), warp tile 32x64.
// Loader pre-splits fp32 -> bf16 hi/lo once per value into ldmatrix-friendly SMEM:
//   A: 128 rows x 80B  (hi k0..15 @0..32, lo @32..64, pad) - stride 20 words
//   B: 16 k-rows x 528B (hi n0..127 @0..256, lo @256..512, pad) - stride 132 words
// Both strides give conflict-free ldmatrix phases. Mainloop: 12 LDSM.x4 + 24 HMMA.
#define CKE 16
#define ASTR 80
#define BSTR 528
#define A_STAGE (128 * ASTR)   // 10240 B
#define B_STAGE (16 * BSTR)    // 8448 B

// MODE 0 (fc1): A = gathered x rows [*,768], B = W1[e] [768,3072]; epi: g_H = gelu(acc+b1)
// MODE 1 (fc2): A = g_H [*,3072],          B = W2[e] [3072,768]; epi: out[tok] += gate*exp(acc+b2)
template <int MODE>
__global__ __launch_bounds__(256, 1)
void moe_mma_kernel(const float* __restrict__ x, const float* __restrict__ W,
                    const float* __restrict__ bias, int e, float* __restrict__ out) {
    int cnt = g_count[e];
    int row0 = blockIdx.y * 128;
    if (row0 >= cnt) return;
    int col0 = blockIdx.x * 128;

    const int KE = (MODE == 0) ? KDIM : KHID;   // reduction length
    const int NB = (MODE == 0) ? KHID : KDIM;   // output width (B row stride)

    __shared__ __align__(16) char sAbuf[2 * A_STAGE];
    __shared__ __align__(16) char sBbuf[2 * B_STAGE];
    __shared__ float s_bias[128];

    uint32_t Abase = smem_u32(sAbuf);
    uint32_t Bbase = smem_u32(sBbuf);

    int tid = threadIdx.x, wid = tid >> 5, lane = tid & 31;
    int wm = (wid & 3) * 32, wn = (wid >> 2) * 64;   // 4x2 warp grid, 32x64 tiles
    int g = lane >> 2, t4 = lane & 3;

    if (tid < 128) s_bias[tid] = bias[(size_t)e * NB + col0 + tid];

    // ---- per-lane ldmatrix base addresses (within stage 0) ----
    int mi = lane >> 3, rr = lane & 7;
    // A x4: m0=(rows+rr,k0-7) m1=(rows+8+rr,k0-7) m2=(+rr,k8-15) m3=(+8+rr,k8-15)
    uint32_t aAddr = Abase + (uint32_t)((wm + ((mi & 1) << 3) + rr) * ASTR + ((mi >> 1) << 4));
    // B x4 (trans): m0=(k rr, n+0-7) m1=(k 8+rr, n+0-7) m2=(k rr, n+8-15) m3=(k 8+rr, n+8-15)
    uint32_t bAddr = Bbase + (uint32_t)((((mi & 1) << 3) + rr) * BSTR + (wn + ((mi >> 1) << 3)) * 2);

    // ---- A loader: thread -> quad q (k 4q..4q+3), rows r0 and r0+64 ----
    int q = tid & 3, r0 = tid >> 2;
    const float *aSrc0, *aSrc1;
    if (MODE == 0) {
        int ga0 = row0 + r0, ga1 = row0 + r0 + 64;
        int tok0 = g_tok[e * NTOK + (ga0 < cnt ? ga0 : row0)];
        int tok1 = g_tok[e * NTOK + (ga1 < cnt ? ga1 : row0)];
        aSrc0 = x + (size_t)tok0 * KDIM + q * 4;
        aSrc1 = x + (size_t)tok1 * KDIM + q * 4;
    } else {
        aSrc0 = g_H + (size_t)(row0 + r0) * KHID + q * 4;       // rows >= cnt: finite garbage
        aSrc1 = g_H + (size_t)(row0 + r0 + 64) * KHID + q * 4;
    }
    // ---- B loader: thread -> k-row kr, n segment seg (8 cols) ----
    int kr = tid >> 4, seg = tid & 15;
    const float* bSrc = W + (size_t)e * KDIM * KHID + (size_t)kr * NB + col0 + seg * 8;

    float4 va0, va1, vb0, vb1;
    auto ldg = [&](int c) {
        va0 = *(const float4*)(aSrc0 + c * CKE);
        va1 = *(const float4*)(aSrc1 + c * CKE);
        const float* bp = bSrc + (size_t)c * CKE * NB;
        vb0 = *(const float4*)bp;
        vb1 = *(const float4*)(bp + 4);
    };
    auto sts = [&](int s) {
        char* Ab = sAbuf + s * A_STAGE;
        char* Bb = sBbuf + s * B_STAGE;
        uint32_t h0, l0, h1, l1, h2, l2, h3, l3;
        // A rows r0 and r0+64: hi pair-words at row*80 + q*8, lo at +32
        split2(va0.x, va0.y, h0, l0); split2(va0.z, va0.w, h1, l1);
        *(uint2*)(Ab + r0 * ASTR + q * 8)      = make_uint2(h0, h1);
        *(uint2*)(Ab + r0 * ASTR + 32 + q * 8) = make_uint2(l0, l1);
        split2(va1.x, va1.y, h0, l0); split2(va1.z, va1.w, h1, l1);
        *(uint2*)(Ab + (r0 + 64) * ASTR + q * 8)      = make_uint2(h0, h1);
        *(uint2*)(Ab + (r0 + 64) * ASTR + 32 + q * 8) = make_uint2(l0, l1);
        // B k-row kr, n seg*8..+7: hi 16B at kr*528 + seg*16, lo at +256
        split2(vb0.x, vb0.y, h0, l0); split2(vb0.z, vb0.w, h1, l1);
        split2(vb1.x, vb1.y, h2, l2); split2(vb1.z, vb1.w, h3, l3);
        *(uint4*)(Bb + kr * BSTR + seg * 16)       = make_uint4(h0, h1, h2, h3);
        *(uint4*)(Bb + kr * BSTR + 256 + seg * 16) = make_uint4(l0, l1, l2, l3);
    };

    float acc[2][8][4];
#pragma unroll
    for (int i = 0; i < 2; i++)
#pragma unroll
        for (int j = 0; j < 8; j++)
#pragma unroll
            for (int k = 0; k < 4; k++) acc[i][j][k] = 0.f;

    const int NC = KE / CKE;
    ldg(0);
    sts(0);

    for (int c = 0; c < NC; c++) {
        __syncthreads();
        if (c + 1 < NC) ldg(c + 1);

        uint32_t stA = aAddr + (c & 1) * A_STAGE;
        uint32_t stB = bAddr + (c & 1) * B_STAGE;

        uint32_t ah[2][4], al[2][4];
#pragma unroll
        for (int mt = 0; mt < 2; mt++) {
            ldsm4(ah[mt], stA + mt * (16 * ASTR));
            ldsm4(al[mt], stA + mt * (16 * ASTR) + 32);
        }
#pragma unroll
        for (int np = 0; np < 4; np++) {
            uint32_t bh[4], bl[4];
            ldsm4t(bh, stB + np * 32);
            ldsm4t(bl, stB + np * 32 + 256);
#pragma unroll
            for (int mt = 0; mt < 2; mt++) {
                mma16816(acc[mt][np * 2 + 0], ah[mt], bh[0], bh[1]);
                mma16816(acc[mt][np * 2 + 1], ah[mt], bh[2], bh[3]);
                mma16816(acc[mt][np * 2 + 0], al[mt], bh[0], bh[1]);
                mma16816(acc[mt][np * 2 + 1], al[mt], bh[2], bh[3]);
                mma16816(acc[mt][np * 2 + 0], ah[mt], bl[0], bl[1]);
                mma16816(acc[mt][np * 2 + 1], ah[mt], bl[2], bl[3]);
            }
        }
        if (c + 1 < NC) sts((c + 1) & 1);
    }

    // ---- epilogue: fragment rows g / g+8; cols wn + nj*8 + 2*t4 + {0,1}
#pragma unroll
    for (int mt = 0; mt < 2; mt++) {
        int gr0 = row0 + wm + mt * 16 + g;
        int gr1 = gr0 + 8;
        bool a0 = gr0 < cnt, a1 = gr1 < cnt;
        int tok0 = 0, tok1 = 0; float gt0 = 0.f, gt1 = 0.f;
        if (MODE == 1) {
            if (a0) { tok0 = g_tok[e * NTOK + gr0]; gt0 = g_gate[e * NTOK + gr0]; }
            if (a1) { tok1 = g_tok[e * NTOK + gr1]; gt1 = g_gate[e * NTOK + gr1]; }
        }
#pragma unroll
        for (int nj = 0; nj < 8; nj++) {
            int cloc = wn + nj * 8 + 2 * t4;
            float b0v = s_bias[cloc], b1v = s_bias[cloc + 1];
            if (MODE == 0) {
                size_t o0 = (size_t)gr0 * KHID + col0 + cloc;
                size_t o1 = (size_t)gr1 * KHID + col0 + cloc;
                if (a0) {
                    g_H[o0]     = gelu_erf(acc[mt][nj][0] + b0v);
                    g_H[o0 + 1] = gelu_erf(acc[mt][nj][1] + b1v);
                }
                if (a1) {
                    g_H[o1]     = gelu_erf(acc[mt][nj][2] + b0v);
                    g_H[o1 + 1] = gelu_erf(acc[mt][nj][3] + b1v);
                }
            } else {
                int cb = col0 + cloc;
                if (a0) {
                    float* op = out + (size_t)tok0 * KDIM + cb;
                    op[0] += gt0 * expf(acc[mt][nj][0] + b0v);
                    op[1] += gt0 * expf(acc[mt][nj][1] + b1v);
                }
                if (a1) {
                    float* op = out + (size_t)tok1 * KDIM + cb;
                    op[0] += gt1 * expf(acc[mt][nj][2] + b0v);
                    op[1] += gt1 * expf(acc[mt][nj][3] + b1v);
                }
            }
        }
    }
}

// ---------------------------------------------------------------------------
__global__ void finalize_kernel(float* __restrict__ out, int n) {
    int i = blockIdx.x * blockDim.x + threadIdx.x;
    if (i < n) {
        float v = out[i];
        out[i] = logf(v == 0.0f ? 2.2204460492503131e-16f : v);
    }
}

// ---------------------------------------------------------------------------
extern "C" void kernel_launch(void* const* d_in, const int* in_sizes, int n_in,
                              void* d_out, int out_size) {
    const float* x  = (const float*)d_in[0];
    const float* wg = (const float*)d_in[1];
    const float* W1 = (const float*)d_in[2];
    const float* b1 = (const float*)d_in[3];
    const float* W2 = (const float*)d_in[4];
    const float* b2 = (const float*)d_in[5];
    float* out = (float*)d_out;

    cudaMemsetAsync(out, 0, (size_t)NTOK * KDIM * sizeof(float), 0);
    zero_counts_kernel<<<1, 32>>>();
    gating_kernel<<<(NTOK * 32 + 255) / 256, 256>>>(x, wg);

    for (int e = 0; e < NEXP; e++) {
        dim3 g1(KHID / 128, NTOK / 128);   // (24, 128)
        moe_mma_kernel<0><<<g1, 256>>>(x, W1, b1, e, out);
        dim3 g2(KDIM / 128, NTOK / 128);   // (6, 128)
        moe_mma_kernel<1><<<g2, 256>>>(g_H, W2, b2, e, out);
    }

    finalize_kernel<<<(NTOK * KDIM + 255) / 256, 256>>>(out, NTOK * KDIM);
}